// round 3
// baseline (speedup 1.0000x reference)
#include <cuda_runtime.h>
#include <cuda_fp16.h>
#include <stdint.h>

// Fixed problem shapes
#define B_CONST     16
#define N_CONST     2048
#define S_CONST     4096
#define D_CONST     128
#define VOCAB_CONST 50257
#define NNZ_CONST   1048576
#define ROWS        (B_CONST * N_CONST)     // 32768 output rows
#define CAP         128                     // bucket capacity (Poisson(32); overflow ~ e^-81)

#define FILL_THREADS  NNZ_CONST
#define FILL_BLOCKS   (FILL_THREADS / 256)                    // 4096
#define CONV_ELEMS    ((size_t)VOCAB_CONST * D_CONST / 4)     // 1,608,224 float4 groups
#define CONV_BLOCKS   ((int)((CONV_ELEMS + 255) / 256))       // 6283

// Static scratch (allocation-free rule: __device__ globals)
__device__ uint2  g_bucket[(size_t)ROWS * CAP];               // 32 MB: (token, val bits)
__device__ int    g_cursor[ROWS];                             // zero-init at load; accumulate resets
__device__ __half g_htable[(size_t)VOCAB_CONST * D_CONST];    // 12.9 MB fp16 shadow of emb_table

// ---------------------------------------------------------------------------
// Phase 1 (fused): blocks [0, FILL_BLOCKS) bucket the nnz entries;
// blocks [FILL_BLOCKS, ...) convert emb_table fp32 -> fp16 shadow.
// The two halves are independent; accumulate depends on both.
// ---------------------------------------------------------------------------
__global__ __launch_bounds__(256) void prep_kernel(
    const int*   __restrict__ subnode_ids,
    const int*   __restrict__ mask_batch,
    const int*   __restrict__ mask_node,
    const int*   __restrict__ mask_subnode,
    const float* __restrict__ mask_values,
    const float* __restrict__ emb_table)
{
    const int blk = blockIdx.x;
    if (blk < FILL_BLOCKS) {
        // ---- fill ----
        const int i = blk * 256 + threadIdx.x;
        const int   b    = __ldg(mask_batch   + i);
        const int   node = __ldg(mask_node    + i);
        const int   sub  = __ldg(mask_subnode + i);
        const float val  = __ldg(mask_values  + i);
        const int   tok  = __ldg(subnode_ids + b * S_CONST + sub);

        const int row = b * N_CONST + node;
        const int pos = atomicAdd(&g_cursor[row], 1);
        if (pos < CAP) {
            uint2 e;
            e.x = (unsigned)tok;
            e.y = __float_as_uint(val);
            g_bucket[(size_t)row * CAP + pos] = e;
        }
    } else {
        // ---- convert fp32 table -> fp16 shadow ----
        const size_t j = (size_t)(blk - FILL_BLOCKS) * 256 + threadIdx.x;
        if (j < CONV_ELEMS) {
            const float4 f = __ldg(reinterpret_cast<const float4*>(emb_table) + j);
            __half2 h0 = __float22half2_rn(make_float2(f.x, f.y));
            __half2 h1 = __float22half2_rn(make_float2(f.z, f.w));
            uint2 u;
            u.x = *reinterpret_cast<unsigned*>(&h0);
            u.y = *reinterpret_cast<unsigned*>(&h1);
            reinterpret_cast<uint2*>(g_htable)[j] = u;
        }
    }
}

// ---------------------------------------------------------------------------
// Phase 2: one warp per output row; lane l owns floats [4l, 4l+4).
// fp16 gathers (8 B/lane/entry), fp32 register accumulation, single STG.128.
// Also resets the row cursor for the next graph replay.
// ---------------------------------------------------------------------------
__global__ __launch_bounds__(256) void accumulate_kernel(
    float* __restrict__ out)   // [B*N, D]
{
    const int gtid = blockIdx.x * blockDim.x + threadIdx.x;
    const int row  = gtid >> 5;
    const int lane = threadIdx.x & 31;
    if (row >= ROWS) return;

    int cnt = g_cursor[row];
    if (lane == 0) g_cursor[row] = 0;      // reset for next replay
    cnt = cnt < CAP ? cnt : CAP;
    const uint2* __restrict__ p = g_bucket + (size_t)row * CAP;

    float4 acc = make_float4(0.f, 0.f, 0.f, 0.f);

    int i = 0;
    #pragma unroll 1
    for (; i + 2 <= cnt; i += 2) {
        const uint2 e0 = __ldg(p + i);
        const uint2 e1 = __ldg(p + i + 1);
        const uint2 u0 = *reinterpret_cast<const uint2*>(
            g_htable + (size_t)e0.x * D_CONST + lane * 4);
        const uint2 u1 = *reinterpret_cast<const uint2*>(
            g_htable + (size_t)e1.x * D_CONST + lane * 4);
        const float v0 = __uint_as_float(e0.y);
        const float v1 = __uint_as_float(e1.y);

        const float2 a0 = __half22float2(*reinterpret_cast<const __half2*>(&u0.x));
        const float2 a1 = __half22float2(*reinterpret_cast<const __half2*>(&u0.y));
        const float2 c0 = __half22float2(*reinterpret_cast<const __half2*>(&u1.x));
        const float2 c1 = __half22float2(*reinterpret_cast<const __half2*>(&u1.y));

        acc.x = fmaf(v0, a0.x, acc.x); acc.y = fmaf(v0, a0.y, acc.y);
        acc.z = fmaf(v0, a1.x, acc.z); acc.w = fmaf(v0, a1.y, acc.w);
        acc.x = fmaf(v1, c0.x, acc.x); acc.y = fmaf(v1, c0.y, acc.y);
        acc.z = fmaf(v1, c1.x, acc.z); acc.w = fmaf(v1, c1.y, acc.w);
    }
    if (i < cnt) {
        const uint2 e0 = __ldg(p + i);
        const uint2 u0 = *reinterpret_cast<const uint2*>(
            g_htable + (size_t)e0.x * D_CONST + lane * 4);
        const float v0 = __uint_as_float(e0.y);
        const float2 a0 = __half22float2(*reinterpret_cast<const __half2*>(&u0.x));
        const float2 a1 = __half22float2(*reinterpret_cast<const __half2*>(&u0.y));
        acc.x = fmaf(v0, a0.x, acc.x); acc.y = fmaf(v0, a0.y, acc.y);
        acc.z = fmaf(v0, a1.x, acc.z); acc.w = fmaf(v0, a1.y, acc.w);
    }

    reinterpret_cast<float4*>(out)[(size_t)row * (D_CONST / 4) + lane] = acc;
}

// ---------------------------------------------------------------------------
// Inputs (metadata order):
//   0: subnode_ids [B*S] i32, 1: mask_batch [NNZ] i32, 2: mask_node [NNZ] i32,
//   3: mask_subnode [NNZ] i32, 4: mask_values [NNZ] f32, 5: emb_table [VOCAB*D] f32
// Output: [B*N*D] f32
// ---------------------------------------------------------------------------
extern "C" void kernel_launch(void* const* d_in, const int* in_sizes, int n_in,
                              void* d_out, int out_size) {
    const int*   subnode_ids  = (const int*)  d_in[0];
    const int*   mask_batch   = (const int*)  d_in[1];
    const int*   mask_node    = (const int*)  d_in[2];
    const int*   mask_subnode = (const int*)  d_in[3];
    const float* mask_values  = (const float*)d_in[4];
    const float* emb_table    = (const float*)d_in[5];
    float*       out          = (float*)d_out;

    prep_kernel<<<FILL_BLOCKS + CONV_BLOCKS, 256>>>(
        subnode_ids, mask_batch, mask_node, mask_subnode, mask_values, emb_table);

    const long long acc_threads = (long long)ROWS * 32;
    accumulate_kernel<<<(int)((acc_threads + 255) / 256), 256>>>(out);
}

// round 4
// speedup vs baseline: 1.1432x; 1.1432x over previous
#include <cuda_runtime.h>
#include <cuda_fp16.h>
#include <stdint.h>

// Fixed problem shapes
#define B_CONST     16
#define N_CONST     2048
#define S_CONST     4096
#define D_CONST     128
#define VOCAB_CONST 50257
#define NNZ_CONST   1048576
#define ROWS        (B_CONST * N_CONST)     // 32768 output rows
#define CAP         128                     // bucket capacity (Poisson(32); overflow ~ e^-81)

#define FILL_BLOCKS   (NNZ_CONST / 256)                       // 4096
#define CONV_ELEMS    ((size_t)VOCAB_CONST * D_CONST / 4)     // float4 groups
#define CONV_BLOCKS   ((int)((CONV_ELEMS + 255) / 256))

// Static scratch (allocation-free rule: __device__ globals)
__device__ uint2  g_bucket[(size_t)ROWS * CAP];               // 32 MB: (token, val bits)
__device__ int    g_cursor[ROWS];                             // zero at load; accumulate resets
__device__ __half g_htable[(size_t)VOCAB_CONST * D_CONST];    // 12.9 MB fp16 shadow

// ---------------------------------------------------------------------------
// Phase 1 (fused): blocks [0, FILL_BLOCKS) bucket nnz entries;
// remaining blocks convert emb_table fp32 -> fp16.
// ---------------------------------------------------------------------------
__global__ __launch_bounds__(256) void prep_kernel(
    const int*   __restrict__ subnode_ids,
    const int*   __restrict__ mask_batch,
    const int*   __restrict__ mask_node,
    const int*   __restrict__ mask_subnode,
    const float* __restrict__ mask_values,
    const float* __restrict__ emb_table)
{
    const int blk = blockIdx.x;
    if (blk < FILL_BLOCKS) {
        const int i = blk * 256 + threadIdx.x;
        const int   b    = __ldg(mask_batch   + i);
        const int   node = __ldg(mask_node    + i);
        const int   sub  = __ldg(mask_subnode + i);
        const float val  = __ldg(mask_values  + i);
        const int   tok  = __ldg(subnode_ids + b * S_CONST + sub);

        const int row = b * N_CONST + node;
        const int pos = atomicAdd(&g_cursor[row], 1);
        if (pos < CAP) {
            uint2 e;
            e.x = (unsigned)tok;
            e.y = __float_as_uint(val);
            g_bucket[(size_t)row * CAP + pos] = e;
        }
    } else {
        const size_t j = (size_t)(blk - FILL_BLOCKS) * 256 + threadIdx.x;
        if (j < CONV_ELEMS) {
            const float4 f = __ldg(reinterpret_cast<const float4*>(emb_table) + j);
            __half2 h0 = __float22half2_rn(make_float2(f.x, f.y));
            __half2 h1 = __float22half2_rn(make_float2(f.z, f.w));
            uint2 u;
            u.x = *reinterpret_cast<unsigned*>(&h0);
            u.y = *reinterpret_cast<unsigned*>(&h1);
            reinterpret_cast<uint2*>(g_htable)[j] = u;
        }
    }
}

// ---------------------------------------------------------------------------
// Phase 2: one warp per output row; lane l owns floats [4l, 4l+4).
// Metadata loaded in bulk (1 coalesced LDG.64 per 32 entries), broadcast via
// shuffles -> 4 fully independent gathers in flight per iteration.
// Lanes past the batch hold (0,0): harmless zero-FMA gathers from row 0.
// ---------------------------------------------------------------------------
__global__ __launch_bounds__(256) void accumulate_kernel(
    float* __restrict__ out)   // [B*N, D]
{
    const int gtid = blockIdx.x * blockDim.x + threadIdx.x;
    const int row  = gtid >> 5;
    const int lane = threadIdx.x & 31;
    if (row >= ROWS) return;

    int cnt = g_cursor[row];
    if (lane == 0) g_cursor[row] = 0;      // reset for next graph replay
    cnt = cnt < CAP ? cnt : CAP;
    const uint2* __restrict__ p = g_bucket + (size_t)row * CAP;

    float4 acc = make_float4(0.f, 0.f, 0.f, 0.f);
    const __half* __restrict__ tab = g_htable;
    const int doff = lane * 4;

    for (int base = 0; base < cnt; base += 32) {
        int m = cnt - base;
        if (m > 32) m = 32;
        uint2 e = make_uint2(0u, 0u);
        if (lane < m) e = __ldg(p + base + lane);
        const int mm = (m + 3) & ~3;       // pad to multiple of 4 (zero entries)

        for (int j = 0; j < mm; j += 4) {
            unsigned tok0 = __shfl_sync(0xffffffffu, e.x, j + 0);
            unsigned tok1 = __shfl_sync(0xffffffffu, e.x, j + 1);
            unsigned tok2 = __shfl_sync(0xffffffffu, e.x, j + 2);
            unsigned tok3 = __shfl_sync(0xffffffffu, e.x, j + 3);
            float v0 = __uint_as_float(__shfl_sync(0xffffffffu, e.y, j + 0));
            float v1 = __uint_as_float(__shfl_sync(0xffffffffu, e.y, j + 1));
            float v2 = __uint_as_float(__shfl_sync(0xffffffffu, e.y, j + 2));
            float v3 = __uint_as_float(__shfl_sync(0xffffffffu, e.y, j + 3));

            // 4 independent 8B gathers (no memory dependency between them)
            const uint2 u0 = *reinterpret_cast<const uint2*>(tab + (size_t)tok0 * D_CONST + doff);
            const uint2 u1 = *reinterpret_cast<const uint2*>(tab + (size_t)tok1 * D_CONST + doff);
            const uint2 u2 = *reinterpret_cast<const uint2*>(tab + (size_t)tok2 * D_CONST + doff);
            const uint2 u3 = *reinterpret_cast<const uint2*>(tab + (size_t)tok3 * D_CONST + doff);

            float2 a, c;
            a = __half22float2(*reinterpret_cast<const __half2*>(&u0.x));
            c = __half22float2(*reinterpret_cast<const __half2*>(&u0.y));
            acc.x = fmaf(v0, a.x, acc.x); acc.y = fmaf(v0, a.y, acc.y);
            acc.z = fmaf(v0, c.x, acc.z); acc.w = fmaf(v0, c.y, acc.w);

            a = __half22float2(*reinterpret_cast<const __half2*>(&u1.x));
            c = __half22float2(*reinterpret_cast<const __half2*>(&u1.y));
            acc.x = fmaf(v1, a.x, acc.x); acc.y = fmaf(v1, a.y, acc.y);
            acc.z = fmaf(v1, c.x, acc.z); acc.w = fmaf(v1, c.y, acc.w);

            a = __half22float2(*reinterpret_cast<const __half2*>(&u2.x));
            c = __half22float2(*reinterpret_cast<const __half2*>(&u2.y));
            acc.x = fmaf(v2, a.x, acc.x); acc.y = fmaf(v2, a.y, acc.y);
            acc.z = fmaf(v2, c.x, acc.z); acc.w = fmaf(v2, c.y, acc.w);

            a = __half22float2(*reinterpret_cast<const __half2*>(&u3.x));
            c = __half22float2(*reinterpret_cast<const __half2*>(&u3.y));
            acc.x = fmaf(v3, a.x, acc.x); acc.y = fmaf(v3, a.y, acc.y);
            acc.z = fmaf(v3, c.x, acc.z); acc.w = fmaf(v3, c.y, acc.w);
        }
    }

    reinterpret_cast<float4*>(out)[(size_t)row * (D_CONST / 4) + lane] = acc;
}

// ---------------------------------------------------------------------------
// Inputs (metadata order):
//   0: subnode_ids [B*S] i32, 1: mask_batch [NNZ] i32, 2: mask_node [NNZ] i32,
//   3: mask_subnode [NNZ] i32, 4: mask_values [NNZ] f32, 5: emb_table [VOCAB*D] f32
// Output: [B*N*D] f32
// ---------------------------------------------------------------------------
extern "C" void kernel_launch(void* const* d_in, const int* in_sizes, int n_in,
                              void* d_out, int out_size) {
    const int*   subnode_ids  = (const int*)  d_in[0];
    const int*   mask_batch   = (const int*)  d_in[1];
    const int*   mask_node    = (const int*)  d_in[2];
    const int*   mask_subnode = (const int*)  d_in[3];
    const float* mask_values  = (const float*)d_in[4];
    const float* emb_table    = (const float*)d_in[5];
    float*       out          = (float*)d_out;

    prep_kernel<<<FILL_BLOCKS + CONV_BLOCKS, 256>>>(
        subnode_ids, mask_batch, mask_node, mask_subnode, mask_values, emb_table);

    const long long acc_threads = (long long)ROWS * 32;
    accumulate_kernel<<<(int)((acc_threads + 255) / 256), 256>>>(out);
}

// round 5
// speedup vs baseline: 1.2173x; 1.0648x over previous
#include <cuda_runtime.h>
#include <cuda_fp16.h>
#include <stdint.h>

// Fixed problem shapes
#define B_CONST     16
#define N_CONST     2048
#define S_CONST     4096
#define D_CONST     128
#define VOCAB_CONST 50257
#define NNZ_CONST   1048576
#define ROWS        (B_CONST * N_CONST)     // 32768 output rows
#define CAP         128                     // bucket capacity (Poisson(32); overflow ~ e^-81)

#define FILL_BLOCKS   (NNZ_CONST / 256)                       // 4096
#define CONV_ELEMS    ((size_t)VOCAB_CONST * D_CONST / 4)     // float4 groups
#define CONV_BLOCKS   ((int)((CONV_ELEMS + 255) / 256))

// Static scratch (__device__ globals; zero-initialized at module load).
// Bucket entry: .x = token id, .y = half2(v, v) bits. Slots beyond a row's
// count are NEVER written (cnt is deterministic per replay) -> stay zero,
// so padded loop iterations gather row 0 with weight 0 (harmless).
__device__ uint2  g_bucket[(size_t)ROWS * CAP];               // 32 MB
__device__ int    g_cursor[ROWS];
__device__ __half g_htable[(size_t)VOCAB_CONST * D_CONST];    // 12.9 MB fp16 shadow

// ---------------------------------------------------------------------------
// Phase 1 (fused): blocks [0, FILL_BLOCKS) bucket nnz entries (val packed as
// half2(v,v)); remaining blocks convert emb_table fp32 -> fp16 shadow.
// ---------------------------------------------------------------------------
__global__ __launch_bounds__(256) void prep_kernel(
    const int*   __restrict__ subnode_ids,
    const int*   __restrict__ mask_batch,
    const int*   __restrict__ mask_node,
    const int*   __restrict__ mask_subnode,
    const float* __restrict__ mask_values,
    const float* __restrict__ emb_table)
{
    const int blk = blockIdx.x;
    if (blk < FILL_BLOCKS) {
        const int i = blk * 256 + threadIdx.x;
        const int   b    = __ldg(mask_batch   + i);
        const int   node = __ldg(mask_node    + i);
        const int   sub  = __ldg(mask_subnode + i);
        const float val  = __ldg(mask_values  + i);
        const int   tok  = __ldg(subnode_ids + b * S_CONST + sub);

        const int row = b * N_CONST + node;
        const int pos = atomicAdd(&g_cursor[row], 1);
        if (pos < CAP) {
            const __half  h  = __float2half_rn(val);
            const __half2 h2 = __halves2half2(h, h);
            uint2 e;
            e.x = (unsigned)tok;
            e.y = *reinterpret_cast<const unsigned*>(&h2);
            g_bucket[(size_t)row * CAP + pos] = e;
        }
    } else {
        const size_t j = (size_t)(blk - FILL_BLOCKS) * 256 + threadIdx.x;
        if (j < CONV_ELEMS) {
            const float4 f = __ldg(reinterpret_cast<const float4*>(emb_table) + j);
            __half2 h0 = __float22half2_rn(make_float2(f.x, f.y));
            __half2 h1 = __float22half2_rn(make_float2(f.z, f.w));
            uint2 u;
            u.x = *reinterpret_cast<unsigned*>(&h0);
            u.y = *reinterpret_cast<unsigned*>(&h1);
            reinterpret_cast<uint2*>(g_htable)[j] = u;
        }
    }
}

// ---------------------------------------------------------------------------
// Phase 2: one warp per output row. Half-warp hw = lane>>4 handles entries
// 2k+hw; lane covers D-halves [8*(lane&15), 8*(lane&15)+8) via one LDG.128
// per 2 entries. HFMA2 accumulation in half2 (no per-element conversion);
// flush to fp32 every 8 entries. Butterfly-merge even/odd partials at end.
// ---------------------------------------------------------------------------
__global__ __launch_bounds__(256) void accumulate_kernel(
    float* __restrict__ out)   // [B*N, D]
{
    const int gtid = blockIdx.x * blockDim.x + threadIdx.x;
    const int row  = gtid >> 5;
    const int lane = threadIdx.x & 31;
    if (row >= ROWS) return;

    int cnt = g_cursor[row];
    if (lane == 0) g_cursor[row] = 0;      // reset for next graph replay
    cnt = cnt < CAP ? cnt : CAP;
    const uint2* __restrict__ p = g_bucket + (size_t)row * CAP;

    const int hw  = lane >> 4;             // 0: even entries, 1: odd entries
    const int sub = lane & 15;             // D-segment [8*sub, 8*sub+8) halves
    const __half* __restrict__ tab = g_htable;

    float facc[8];
    #pragma unroll
    for (int q = 0; q < 8; q++) facc[q] = 0.f;

    for (int base = 0; base < cnt; base += 32) {
        // Entries base..base+31 (slots >= cnt are zero -> weight 0)
        const uint2 e = __ldg(p + base + lane);
        const int nb = cnt - base;          // >0

        #pragma unroll
        for (int g = 0; g < 4; g++) {       // 8 entries per group
            if (g * 8 >= nb) break;

            __half2 hacc0 = __float2half2_rn(0.f);
            __half2 hacc1 = hacc0, hacc2 = hacc0, hacc3 = hacc0;

            #pragma unroll
            for (int L = 0; L < 4; L++) {   // 4 LDG.128 = 8 entries
                const int idx = g * 8 + L * 2 + hw;
                const unsigned tok = __shfl_sync(0xffffffffu, e.x, idx);
                const unsigned vvb = __shfl_sync(0xffffffffu, e.y, idx);
                const __half2 v2 = *reinterpret_cast<const __half2*>(&vvb);

                const uint4 u = *reinterpret_cast<const uint4*>(
                    tab + (size_t)tok * D_CONST + sub * 8);

                hacc0 = __hfma2(v2, *reinterpret_cast<const __half2*>(&u.x), hacc0);
                hacc1 = __hfma2(v2, *reinterpret_cast<const __half2*>(&u.y), hacc1);
                hacc2 = __hfma2(v2, *reinterpret_cast<const __half2*>(&u.z), hacc2);
                hacc3 = __hfma2(v2, *reinterpret_cast<const __half2*>(&u.w), hacc3);
            }

            // Flush half2 partials to fp32 (amortized: 1 cvt + 1 add / entry)
            float2 f;
            f = __half22float2(hacc0); facc[0] += f.x; facc[1] += f.y;
            f = __half22float2(hacc1); facc[2] += f.x; facc[3] += f.y;
            f = __half22float2(hacc2); facc[4] += f.x; facc[5] += f.y;
            f = __half22float2(hacc3); facc[6] += f.x; facc[7] += f.y;
        }
    }

    // Merge even-entry (hw=0) and odd-entry (hw=1) partial sums
    #pragma unroll
    for (int q = 0; q < 8; q++)
        facc[q] += __shfl_xor_sync(0xffffffffu, facc[q], 16);

    // Store: lane(hw,sub) writes float4 at D-offset 8*sub + 4*hw
    float4 st;
    if (hw == 0) st = make_float4(facc[0], facc[1], facc[2], facc[3]);
    else         st = make_float4(facc[4], facc[5], facc[6], facc[7]);
    *reinterpret_cast<float4*>(out + (size_t)row * D_CONST + sub * 8 + hw * 4) = st;
}

// ---------------------------------------------------------------------------
// Inputs (metadata order):
//   0: subnode_ids [B*S] i32, 1: mask_batch [NNZ] i32, 2: mask_node [NNZ] i32,
//   3: mask_subnode [NNZ] i32, 4: mask_values [NNZ] f32, 5: emb_table [VOCAB*D] f32
// Output: [B*N*D] f32
// ---------------------------------------------------------------------------
extern "C" void kernel_launch(void* const* d_in, const int* in_sizes, int n_in,
                              void* d_out, int out_size) {
    const int*   subnode_ids  = (const int*)  d_in[0];
    const int*   mask_batch   = (const int*)  d_in[1];
    const int*   mask_node    = (const int*)  d_in[2];
    const int*   mask_subnode = (const int*)  d_in[3];
    const float* mask_values  = (const float*)d_in[4];
    const float* emb_table    = (const float*)d_in[5];
    float*       out          = (float*)d_out;

    prep_kernel<<<FILL_BLOCKS + CONV_BLOCKS, 256>>>(
        subnode_ids, mask_batch, mask_node, mask_subnode, mask_values, emb_table);

    const long long acc_threads = (long long)ROWS * 32;
    accumulate_kernel<<<(int)((acc_threads + 255) / 256), 256>>>(out);
}

// round 6
// speedup vs baseline: 1.5630x; 1.2840x over previous
#include <cuda_runtime.h>
#include <cuda_fp16.h>
#include <stdint.h>

// Fixed problem shapes
#define B_CONST     16
#define N_CONST     2048
#define S_CONST     4096
#define D_CONST     128
#define VOCAB_CONST 50257
#define NNZ_CONST   1048576
#define ROWS        (B_CONST * N_CONST)     // 32768 output rows
#define CAP         128                     // bucket capacity (Poisson(32); overflow ~ e^-81)

#define FILL_BLOCKS   (NNZ_CONST / 256)                       // 4096
#define CONV_ELEMS    ((size_t)VOCAB_CONST * D_CONST / 4)
#define CONV_BLOCKS   ((int)((CONV_ELEMS + 255) / 256))

// Static scratch (__device__ globals; zero-initialized at module load).
// Bucket entry: .x = token id, .y = half2(v, v) bits. Unwritten slots stay 0.
__device__ uint2  g_bucket[(size_t)ROWS * CAP];               // 32 MB
__device__ int    g_cursor[ROWS];
__device__ __half g_htable[(size_t)VOCAB_CONST * D_CONST];    // 12.9 MB fp16 shadow

// ---------------------------------------------------------------------------
// Phase 1 (fused): fill buckets + convert table to fp16.
// ---------------------------------------------------------------------------
__global__ __launch_bounds__(256) void prep_kernel(
    const int*   __restrict__ subnode_ids,
    const int*   __restrict__ mask_batch,
    const int*   __restrict__ mask_node,
    const int*   __restrict__ mask_subnode,
    const float* __restrict__ mask_values,
    const float* __restrict__ emb_table)
{
    const int blk = blockIdx.x;
    if (blk < FILL_BLOCKS) {
        const int i = blk * 256 + threadIdx.x;
        const int   b    = __ldg(mask_batch   + i);
        const int   node = __ldg(mask_node    + i);
        const int   sub  = __ldg(mask_subnode + i);
        const float val  = __ldg(mask_values  + i);
        const int   tok  = __ldg(subnode_ids + b * S_CONST + sub);

        const int row = b * N_CONST + node;
        const int pos = atomicAdd(&g_cursor[row], 1);
        if (pos < CAP) {
            const __half  h  = __float2half_rn(val);
            const __half2 h2 = __halves2half2(h, h);
            uint2 e;
            e.x = (unsigned)tok;
            e.y = *reinterpret_cast<const unsigned*>(&h2);
            g_bucket[(size_t)row * CAP + pos] = e;
        }
    } else {
        const size_t j = (size_t)(blk - FILL_BLOCKS) * 256 + threadIdx.x;
        if (j < CONV_ELEMS) {
            const float4 f = __ldg(reinterpret_cast<const float4*>(emb_table) + j);
            __half2 h0 = __float22half2_rn(make_float2(f.x, f.y));
            __half2 h1 = __float22half2_rn(make_float2(f.z, f.w));
            uint2 u;
            u.x = *reinterpret_cast<unsigned*>(&h0);
            u.y = *reinterpret_cast<unsigned*>(&h1);
            reinterpret_cast<uint2*>(g_htable)[j] = u;
        }
    }
}

// ---------------------------------------------------------------------------
// Phase 2: TWO warps per row (each takes half the entries). Within a warp,
// half-warp hw takes alternate entries; lane covers D-halves
// [8*(lane&15), 8*(lane&15)+8) via LDG.128. Groups of 8 entries are
// software-pipelined (double-buffered: next group's 4 gathers issue before
// the current group's HFMA2/flush). Partials merged through smem.
// Block = 256 threads = 8 warps = 4 rows.
// ---------------------------------------------------------------------------
__global__ __launch_bounds__(256) void accumulate_kernel(
    float* __restrict__ out)   // [B*N, D]
{
    const int wib  = threadIdx.x >> 5;      // warp in block: 0..7
    const int pr   = wib >> 1;              // row slot in block: 0..3
    const int half = wib & 1;               // which half of the entry list
    const int row  = blockIdx.x * 4 + pr;
    const int lane = threadIdx.x & 31;
    const int hw   = lane >> 4;             // entry parity within group pair
    const int sub  = lane & 15;             // D-segment [8*sub, 8*sub+8) halves

    __shared__ float s_acc[4][D_CONST];

    int cnt = g_cursor[row];
    cnt = cnt < CAP ? cnt : CAP;
    const int hc     = (cnt + 1) >> 1;              // first-half count
    const int my_off = half ? hc : 0;
    const int my_n   = half ? (cnt - hc) : hc;

    const uint2* __restrict__ p = g_bucket + (size_t)row * CAP + my_off;
    const __half* __restrict__ tab = g_htable;

    float facc[8];
    #pragma unroll
    for (int q = 0; q < 8; q++) facc[q] = 0.f;

    // Load group 'G' (8 entries via 4 LDG.128) into buffer slot BUF (literal).
    #define LOADG(BUF, G) do {                                                  \
        _Pragma("unroll")                                                       \
        for (int L = 0; L < 4; L++) {                                           \
            const int idx = (G) * 8 + L * 2 + hw;                               \
            const unsigned tk = __shfl_sync(0xffffffffu, e.x, idx);             \
            const unsigned vv = __shfl_sync(0xffffffffu, e.y, idx);             \
            v2b[BUF][L] = *reinterpret_cast<const __half2*>(&vv);               \
            ub[BUF][L]  = *reinterpret_cast<const uint4*>(                      \
                tab + (size_t)tk * D_CONST + sub * 8);                          \
        }                                                                       \
    } while (0)

    #define CONSUME(BUF) do {                                                   \
        __half2 h0 = __float2half2_rn(0.f), h1 = h0, h2 = h0, h3 = h0;          \
        _Pragma("unroll")                                                       \
        for (int L = 0; L < 4; L++) {                                           \
            const __half2 v2 = v2b[BUF][L];                                     \
            const uint4   u  = ub[BUF][L];                                      \
            h0 = __hfma2(v2, *reinterpret_cast<const __half2*>(&u.x), h0);      \
            h1 = __hfma2(v2, *reinterpret_cast<const __half2*>(&u.y), h1);      \
            h2 = __hfma2(v2, *reinterpret_cast<const __half2*>(&u.z), h2);      \
            h3 = __hfma2(v2, *reinterpret_cast<const __half2*>(&u.w), h3);      \
        }                                                                       \
        float2 f;                                                               \
        f = __half22float2(h0); facc[0] += f.x; facc[1] += f.y;                 \
        f = __half22float2(h1); facc[2] += f.x; facc[3] += f.y;                 \
        f = __half22float2(h2); facc[4] += f.x; facc[5] += f.y;                 \
        f = __half22float2(h3); facc[6] += f.x; facc[7] += f.y;                 \
    } while (0)

    for (int base = 0; base < my_n; base += 32) {
        const int rem = my_n - base;
        const int nb  = rem < 32 ? rem : 32;
        // Masked metadata load: padding lanes get (tok=0, v=0) -> zero FMA.
        uint2 e = make_uint2(0u, 0u);
        if (lane < nb) e = __ldg(p + base + lane);
        const int ngrp = (nb + 7) >> 3;     // 1..4 groups of 8

        uint4   ub[2][4];
        __half2 v2b[2][4];

        LOADG(0, 0);
        int g = 0;
        while (true) {
            if (g + 1 < ngrp) LOADG(1, g + 1);
            CONSUME(0);
            g++;
            if (g >= ngrp) break;
            if (g + 1 < ngrp) LOADG(0, g + 1);
            CONSUME(1);
            g++;
            if (g >= ngrp) break;
        }
    }
    #undef LOADG
    #undef CONSUME

    // Merge even/odd-entry partials across half-warps
    #pragma unroll
    for (int q = 0; q < 8; q++)
        facc[q] += __shfl_xor_sync(0xffffffffu, facc[q], 16);

    float4 st;
    if (hw == 0) st = make_float4(facc[0], facc[1], facc[2], facc[3]);
    else         st = make_float4(facc[4], facc[5], facc[6], facc[7]);

    const int dseg = sub * 8 + hw * 4;      // float offset within the row
    if (half == 0)
        *reinterpret_cast<float4*>(&s_acc[pr][dseg]) = st;
    __syncthreads();
    if (half == 1) {
        const float4 o = *reinterpret_cast<const float4*>(&s_acc[pr][dseg]);
        st.x += o.x; st.y += o.y; st.z += o.z; st.w += o.w;
        *reinterpret_cast<float4*>(out + (size_t)row * D_CONST + dseg) = st;
        if (lane == 0) g_cursor[row] = 0;   // reset for next replay (after all reads)
    }
}

// ---------------------------------------------------------------------------
// Inputs (metadata order):
//   0: subnode_ids [B*S] i32, 1: mask_batch [NNZ] i32, 2: mask_node [NNZ] i32,
//   3: mask_subnode [NNZ] i32, 4: mask_values [NNZ] f32, 5: emb_table [VOCAB*D] f32
// Output: [B*N*D] f32
// ---------------------------------------------------------------------------
extern "C" void kernel_launch(void* const* d_in, const int* in_sizes, int n_in,
                              void* d_out, int out_size) {
    const int*   subnode_ids  = (const int*)  d_in[0];
    const int*   mask_batch   = (const int*)  d_in[1];
    const int*   mask_node    = (const int*)  d_in[2];
    const int*   mask_subnode = (const int*)  d_in[3];
    const float* mask_values  = (const float*)d_in[4];
    const float* emb_table    = (const float*)d_in[5];
    float*       out          = (float*)d_out;

    prep_kernel<<<FILL_BLOCKS + CONV_BLOCKS, 256>>>(
        subnode_ids, mask_batch, mask_node, mask_subnode, mask_values, emb_table);

    accumulate_kernel<<<ROWS / 4, 256>>>(out);
}

// round 7
// speedup vs baseline: 1.7467x; 1.1175x over previous
#include <cuda_runtime.h>
#include <cuda_fp16.h>
#include <stdint.h>

// Fixed problem shapes
#define B_CONST     16
#define N_CONST     2048
#define S_CONST     4096
#define D_CONST     128
#define VOCAB_CONST 50257
#define NNZ_CONST   1048576
#define ROWS        (B_CONST * N_CONST)     // 32768 output rows
#define CAP         128                     // bucket capacity (Poisson(32); overflow ~ e^-81)

#define FILL_BLOCKS   (NNZ_CONST / 256)                       // 4096
#define CONV_ELEMS    ((size_t)VOCAB_CONST * D_CONST / 4)
#define CONV_BLOCKS   ((int)((CONV_ELEMS + 255) / 256))

// Static scratch (__device__ globals; zero-initialized at module load).
// Bucket entry: .x = token id, .y = half2(v, v) bits. Unwritten slots stay 0.
__device__ uint2  g_bucket[(size_t)ROWS * CAP];               // 32 MB
__device__ int    g_cursor[ROWS];
__device__ __half g_htable[(size_t)VOCAB_CONST * D_CONST];    // 12.9 MB fp16 shadow

// ---------------------------------------------------------------------------
// Phase 1 (fused): fill buckets + convert table to fp16.
// ---------------------------------------------------------------------------
__global__ __launch_bounds__(256) void prep_kernel(
    const int*   __restrict__ subnode_ids,
    const int*   __restrict__ mask_batch,
    const int*   __restrict__ mask_node,
    const int*   __restrict__ mask_subnode,
    const float* __restrict__ mask_values,
    const float* __restrict__ emb_table)
{
    const int blk = blockIdx.x;
    if (blk < FILL_BLOCKS) {
        const int i = blk * 256 + threadIdx.x;
        const int   b    = __ldg(mask_batch   + i);
        const int   node = __ldg(mask_node    + i);
        const int   sub  = __ldg(mask_subnode + i);
        const float val  = __ldg(mask_values  + i);
        const int   tok  = __ldg(subnode_ids + b * S_CONST + sub);

        const int row = b * N_CONST + node;
        const int pos = atomicAdd(&g_cursor[row], 1);
        if (pos < CAP) {
            const __half  h  = __float2half_rn(val);
            const __half2 h2 = __halves2half2(h, h);
            uint2 e;
            e.x = (unsigned)tok;
            e.y = *reinterpret_cast<const unsigned*>(&h2);
            g_bucket[(size_t)row * CAP + pos] = e;
        }
    } else {
        const size_t j = (size_t)(blk - FILL_BLOCKS) * 256 + threadIdx.x;
        if (j < CONV_ELEMS) {
            const float4 f = __ldg(reinterpret_cast<const float4*>(emb_table) + j);
            __half2 h0 = __float22half2_rn(make_float2(f.x, f.y));
            __half2 h1 = __float22half2_rn(make_float2(f.z, f.w));
            uint2 u;
            u.x = *reinterpret_cast<unsigned*>(&h0);
            u.y = *reinterpret_cast<unsigned*>(&h1);
            reinterpret_cast<uint2*>(g_htable)[j] = u;
        }
    }
}

// ---------------------------------------------------------------------------
// Phase 2: TWO warps per row; within a warp, half-warp hw takes alternate
// entries, lane covers D-halves [8*(lane&15), 8*(lane&15)+8) via LDG.128.
// 8-entry groups double-buffered (gathers only; values re-shuffled at
// consume time to save registers). __launch_bounds__(256,4) forces <=64 regs
// so 4 blocks (32 warps) fit per SM. Partials merged through smem.
// ---------------------------------------------------------------------------
__global__ __launch_bounds__(256, 4) void accumulate_kernel(
    float* __restrict__ out)   // [B*N, D]
{
    const int wib  = threadIdx.x >> 5;      // warp in block: 0..7
    const int pr   = wib >> 1;              // row slot in block: 0..3
    const int half = wib & 1;               // which half of the entry list
    const int row  = blockIdx.x * 4 + pr;
    const int lane = threadIdx.x & 31;
    const int hw   = lane >> 4;             // entry parity within group
    const int sub  = lane & 15;             // D-segment [8*sub, 8*sub+8) halves

    __shared__ float s_acc[4][D_CONST];

    int cnt = g_cursor[row];
    cnt = cnt < CAP ? cnt : CAP;
    const int hc     = (cnt + 1) >> 1;
    const int my_off = half ? hc : 0;
    const int my_n   = half ? (cnt - hc) : hc;

    const uint2* __restrict__ p = g_bucket + (size_t)row * CAP + my_off;
    const __half* __restrict__ tab = g_htable;

    float facc[8];
    #pragma unroll
    for (int q = 0; q < 8; q++) facc[q] = 0.f;

    // Issue group G's 4 independent LDG.128 into buffer BUF (addresses from
    // token shuffles; no value buffering).
    #define LOADG(BUF, G) do {                                                  \
        _Pragma("unroll")                                                       \
        for (int L = 0; L < 4; L++) {                                           \
            const int idx = (G) * 8 + L * 2 + hw;                               \
            const unsigned tk = __shfl_sync(0xffffffffu, e.x, idx);             \
            ub[BUF][L] = *reinterpret_cast<const uint4*>(                       \
                tab + (size_t)tk * D_CONST + sub * 8);                          \
        }                                                                       \
    } while (0)

    #define CONSUME(BUF, G) do {                                                \
        __half2 h0 = __float2half2_rn(0.f), h1 = h0, h2 = h0, h3 = h0;          \
        _Pragma("unroll")                                                       \
        for (int L = 0; L < 4; L++) {                                           \
            const int idx = (G) * 8 + L * 2 + hw;                               \
            const unsigned vv = __shfl_sync(0xffffffffu, e.y, idx);             \
            const __half2 v2 = *reinterpret_cast<const __half2*>(&vv);          \
            const uint4   u  = ub[BUF][L];                                      \
            h0 = __hfma2(v2, *reinterpret_cast<const __half2*>(&u.x), h0);      \
            h1 = __hfma2(v2, *reinterpret_cast<const __half2*>(&u.y), h1);      \
            h2 = __hfma2(v2, *reinterpret_cast<const __half2*>(&u.z), h2);      \
            h3 = __hfma2(v2, *reinterpret_cast<const __half2*>(&u.w), h3);      \
        }                                                                       \
        float2 f;                                                               \
        f = __half22float2(h0); facc[0] += f.x; facc[1] += f.y;                 \
        f = __half22float2(h1); facc[2] += f.x; facc[3] += f.y;                 \
        f = __half22float2(h2); facc[4] += f.x; facc[5] += f.y;                 \
        f = __half22float2(h3); facc[6] += f.x; facc[7] += f.y;                 \
    } while (0)

    for (int base = 0; base < my_n; base += 32) {
        const int rem = my_n - base;
        const int nb  = rem < 32 ? rem : 32;
        uint2 e = make_uint2(0u, 0u);                 // padding: tok 0, v 0
        if (lane < nb) e = __ldg(p + base + lane);
        const int ngrp = (nb + 7) >> 3;               // 1..4 groups of 8

        uint4 ub[2][4];

        LOADG(0, 0);
        int g = 0;
        while (true) {
            if (g + 1 < ngrp) LOADG(1, g + 1);
            CONSUME(0, g);
            g++;
            if (g >= ngrp) break;
            if (g + 1 < ngrp) LOADG(0, g + 1);
            CONSUME(1, g);
            g++;
            if (g >= ngrp) break;
        }
    }
    #undef LOADG
    #undef CONSUME

    // Merge even/odd-entry partials across half-warps
    #pragma unroll
    for (int q = 0; q < 8; q++)
        facc[q] += __shfl_xor_sync(0xffffffffu, facc[q], 16);

    float4 st;
    if (hw == 0) st = make_float4(facc[0], facc[1], facc[2], facc[3]);
    else         st = make_float4(facc[4], facc[5], facc[6], facc[7]);

    const int dseg = sub * 8 + hw * 4;      // float offset within the row
    if (half == 0)
        *reinterpret_cast<float4*>(&s_acc[pr][dseg]) = st;
    __syncthreads();
    if (half == 1) {
        const float4 o = *reinterpret_cast<const float4*>(&s_acc[pr][dseg]);
        st.x += o.x; st.y += o.y; st.z += o.z; st.w += o.w;
        *reinterpret_cast<float4*>(out + (size_t)row * D_CONST + dseg) = st;
        if (lane == 0) g_cursor[row] = 0;   // reset for next replay
    }
}

// ---------------------------------------------------------------------------
// Inputs (metadata order):
//   0: subnode_ids [B*S] i32, 1: mask_batch [NNZ] i32, 2: mask_node [NNZ] i32,
//   3: mask_subnode [NNZ] i32, 4: mask_values [NNZ] f32, 5: emb_table [VOCAB*D] f32
// Output: [B*N*D] f32
// ---------------------------------------------------------------------------
extern "C" void kernel_launch(void* const* d_in, const int* in_sizes, int n_in,
                              void* d_out, int out_size) {
    const int*   subnode_ids  = (const int*)  d_in[0];
    const int*   mask_batch   = (const int*)  d_in[1];
    const int*   mask_node    = (const int*)  d_in[2];
    const int*   mask_subnode = (const int*)  d_in[3];
    const float* mask_values  = (const float*)d_in[4];
    const float* emb_table    = (const float*)d_in[5];
    float*       out          = (float*)d_out;

    prep_kernel<<<FILL_BLOCKS + CONV_BLOCKS, 256>>>(
        subnode_ids, mask_batch, mask_node, mask_subnode, mask_values, emb_table);

    accumulate_kernel<<<ROWS / 4, 256>>>(out);
}

// round 8
// speedup vs baseline: 1.9412x; 1.1114x over previous
#include <cuda_runtime.h>
#include <cuda_fp16.h>
#include <stdint.h>

// Fixed problem shapes
#define B_CONST     16
#define N_CONST     2048
#define S_CONST     4096
#define D_CONST     128
#define VOCAB_CONST 50257
#define NNZ_CONST   1048576
#define ROWS        (B_CONST * N_CONST)     // 32768 output rows
#define CAP         128                     // bucket capacity (Poisson(32); overflow ~ e^-81)

#define FILL_BLOCKS   (NNZ_CONST / 256)                       // 4096
#define CONV_ELEMS8   ((size_t)VOCAB_CONST * D_CONST / 8)     // 8-float groups
#define CONV_BLOCKS   ((int)((CONV_ELEMS8 + 255) / 256))

// Static scratch (__device__ globals; zero-initialized at module load).
// Bucket entry: .x = token id, .y = half2(v, v) bits. Unwritten slots stay 0.
__device__ uint2  g_bucket[(size_t)ROWS * CAP];               // 32 MB
__device__ int    g_cursor[ROWS];
__device__ __half g_htable[(size_t)VOCAB_CONST * D_CONST];    // 12.9 MB fp16 shadow

// ---------------------------------------------------------------------------
// Phase 1 (fused): fill buckets + convert table to fp16 (8 floats/thread).
// ---------------------------------------------------------------------------
__global__ __launch_bounds__(256) void prep_kernel(
    const int*   __restrict__ subnode_ids,
    const int*   __restrict__ mask_batch,
    const int*   __restrict__ mask_node,
    const int*   __restrict__ mask_subnode,
    const float* __restrict__ mask_values,
    const float* __restrict__ emb_table)
{
    const int blk = blockIdx.x;
    if (blk < FILL_BLOCKS) {
        const int i = blk * 256 + threadIdx.x;
        const int   b    = __ldg(mask_batch   + i);
        const int   node = __ldg(mask_node    + i);
        const int   sub  = __ldg(mask_subnode + i);
        const float val  = __ldg(mask_values  + i);
        const int   tok  = __ldg(subnode_ids + b * S_CONST + sub);

        const int row = b * N_CONST + node;
        const int pos = atomicAdd(&g_cursor[row], 1);
        if (pos < CAP) {
            const __half  h  = __float2half_rn(val);
            const __half2 h2 = __halves2half2(h, h);
            uint2 e;
            e.x = (unsigned)tok;
            e.y = *reinterpret_cast<const unsigned*>(&h2);
            g_bucket[(size_t)row * CAP + pos] = e;
        }
    } else {
        const size_t j = (size_t)(blk - FILL_BLOCKS) * 256 + threadIdx.x;
        if (j < CONV_ELEMS8) {
            const float4 f0 = __ldg(reinterpret_cast<const float4*>(emb_table) + 2 * j);
            const float4 f1 = __ldg(reinterpret_cast<const float4*>(emb_table) + 2 * j + 1);
            __half2 h0 = __float22half2_rn(make_float2(f0.x, f0.y));
            __half2 h1 = __float22half2_rn(make_float2(f0.z, f0.w));
            __half2 h2 = __float22half2_rn(make_float2(f1.x, f1.y));
            __half2 h3 = __float22half2_rn(make_float2(f1.z, f1.w));
            uint4 u;
            u.x = *reinterpret_cast<unsigned*>(&h0);
            u.y = *reinterpret_cast<unsigned*>(&h1);
            u.z = *reinterpret_cast<unsigned*>(&h2);
            u.w = *reinterpret_cast<unsigned*>(&h3);
            reinterpret_cast<uint4*>(g_htable)[j] = u;
        }
    }
}

// ---------------------------------------------------------------------------
// Phase 2: TWO warps per row (each half the entries). One entry = one LDG.64
// by the FULL warp (32 lanes x 8B = the whole 256B fp16 row). 4-entry groups
// double-buffered -> 8 independent loads in flight per warp with only
// uint2 ub[2][4] (16 regs) of buffer. Block = 128 threads (4 warps, 2 rows),
// 12 blocks/SM target -> 48 warps/SM. Partials merged through smem.
// ---------------------------------------------------------------------------
__global__ __launch_bounds__(128, 12) void accumulate_kernel(
    float* __restrict__ out)   // [B*N, D]
{
    const int wib  = threadIdx.x >> 5;      // warp in block: 0..3
    const int pr   = wib >> 1;              // row slot in block: 0..1
    const int half = wib & 1;               // which half of the entry list
    const int row  = blockIdx.x * 2 + pr;
    const int lane = threadIdx.x & 31;      // D-halves [4*lane, 4*lane+4)

    __shared__ float s_acc[2][D_CONST];

    int cnt = g_cursor[row];
    cnt = cnt < CAP ? cnt : CAP;
    const int hc     = (cnt + 1) >> 1;
    const int my_off = half ? hc : 0;
    const int my_n   = half ? (cnt - hc) : hc;

    const uint2* __restrict__ p = g_bucket + (size_t)row * CAP + my_off;
    const __half* __restrict__ tab = g_htable;

    float facc[4];
    #pragma unroll
    for (int q = 0; q < 4; q++) facc[q] = 0.f;

    // Group G = 4 entries; one LDG.64 per entry (full warp reads the row).
    #define LOADG(BUF, G) do {                                                  \
        _Pragma("unroll")                                                       \
        for (int L = 0; L < 4; L++) {                                           \
            const unsigned tk = __shfl_sync(0xffffffffu, e.x, (G) * 4 + L);     \
            ub[BUF][L] = *reinterpret_cast<const uint2*>(                       \
                tab + (size_t)tk * D_CONST + lane * 4);                         \
        }                                                                       \
    } while (0)

    #define CONSUME(BUF, G) do {                                                \
        __half2 h0 = __float2half2_rn(0.f), h1 = h0;                            \
        _Pragma("unroll")                                                       \
        for (int L = 0; L < 4; L++) {                                           \
            const unsigned vv = __shfl_sync(0xffffffffu, e.y, (G) * 4 + L);     \
            const __half2 v2 = *reinterpret_cast<const __half2*>(&vv);          \
            const uint2   u  = ub[BUF][L];                                      \
            h0 = __hfma2(v2, *reinterpret_cast<const __half2*>(&u.x), h0);      \
            h1 = __hfma2(v2, *reinterpret_cast<const __half2*>(&u.y), h1);      \
        }                                                                       \
        float2 f;                                                               \
        f = __half22float2(h0); facc[0] += f.x; facc[1] += f.y;                 \
        f = __half22float2(h1); facc[2] += f.x; facc[3] += f.y;                 \
    } while (0)

    for (int base = 0; base < my_n; base += 32) {
        const int rem = my_n - base;
        const int nb  = rem < 32 ? rem : 32;
        uint2 e = make_uint2(0u, 0u);                 // padding: tok 0, v 0
        if (lane < nb) e = __ldg(p + base + lane);
        const int ngrp = (nb + 3) >> 2;               // 1..8 groups of 4

        uint2 ub[2][4];

        LOADG(0, 0);
        int g = 0;
        while (true) {
            if (g + 1 < ngrp) LOADG(1, g + 1);
            CONSUME(0, g);
            g++;
            if (g >= ngrp) break;
            if (g + 1 < ngrp) LOADG(0, g + 1);
            CONSUME(1, g);
            g++;
            if (g >= ngrp) break;
        }
    }
    #undef LOADG
    #undef CONSUME

    float4 st = make_float4(facc[0], facc[1], facc[2], facc[3]);

    if (half == 0)
        *reinterpret_cast<float4*>(&s_acc[pr][lane * 4]) = st;
    __syncthreads();
    if (half == 1) {
        const float4 o = *reinterpret_cast<const float4*>(&s_acc[pr][lane * 4]);
        st.x += o.x; st.y += o.y; st.z += o.z; st.w += o.w;
        *reinterpret_cast<float4*>(out + (size_t)row * D_CONST + lane * 4) = st;
        if (lane == 0) g_cursor[row] = 0;   // reset for next replay
    }
}

// ---------------------------------------------------------------------------
// Inputs (metadata order):
//   0: subnode_ids [B*S] i32, 1: mask_batch [NNZ] i32, 2: mask_node [NNZ] i32,
//   3: mask_subnode [NNZ] i32, 4: mask_values [NNZ] f32, 5: emb_table [VOCAB*D] f32
// Output: [B*N*D] f32
// ---------------------------------------------------------------------------
extern "C" void kernel_launch(void* const* d_in, const int* in_sizes, int n_in,
                              void* d_out, int out_size) {
    const int*   subnode_ids  = (const int*)  d_in[0];
    const int*   mask_batch   = (const int*)  d_in[1];
    const int*   mask_node    = (const int*)  d_in[2];
    const int*   mask_subnode = (const int*)  d_in[3];
    const float* mask_values  = (const float*)d_in[4];
    const float* emb_table    = (const float*)d_in[5];
    float*       out          = (float*)d_out;

    prep_kernel<<<FILL_BLOCKS + CONV_BLOCKS, 256>>>(
        subnode_ids, mask_batch, mask_node, mask_subnode, mask_values, emb_table);

    accumulate_kernel<<<ROWS / 2, 128>>>(out);
}

// round 9
// speedup vs baseline: 2.0109x; 1.0359x over previous
#include <cuda_runtime.h>
#include <cuda_fp16.h>
#include <stdint.h>

// Fixed problem shapes
#define B_CONST     16
#define N_CONST     2048
#define S_CONST     4096
#define D_CONST     128
#define VOCAB_CONST 50257
#define NNZ_CONST   1048576
#define ROWS        (B_CONST * N_CONST)     // 32768 output rows
#define CAP         128                     // bucket capacity (Poisson(32); overflow ~ e^-81)

#define FILL_BLOCKS   (NNZ_CONST / 256)                       // 4096
#define CONV_ELEMS8   ((size_t)VOCAB_CONST * D_CONST / 8)     // 8-float groups
#define CONV_BLOCKS   ((int)((CONV_ELEMS8 + 255) / 256))

// Static scratch (__device__ globals; zero-initialized at module load).
// Bucket entry: .x = token id, .y = half2(v, v) bits. Unwritten slots stay 0.
__device__ uint2  g_bucket[(size_t)ROWS * CAP];               // 32 MB
__device__ int    g_cursor[ROWS];
__device__ __half g_htable[(size_t)VOCAB_CONST * D_CONST];    // 12.9 MB fp16 shadow

// ---------------------------------------------------------------------------
// Phase 1 (fused): fill buckets + convert table to fp16 (8 floats/thread).
// ---------------------------------------------------------------------------
__global__ __launch_bounds__(256) void prep_kernel(
    const int*   __restrict__ subnode_ids,
    const int*   __restrict__ mask_batch,
    const int*   __restrict__ mask_node,
    const int*   __restrict__ mask_subnode,
    const float* __restrict__ mask_values,
    const float* __restrict__ emb_table)
{
    const int blk = blockIdx.x;
    if (blk < FILL_BLOCKS) {
        const int i = blk * 256 + threadIdx.x;
        const int   b    = __ldg(mask_batch   + i);
        const int   node = __ldg(mask_node    + i);
        const int   sub  = __ldg(mask_subnode + i);
        const float val  = __ldg(mask_values  + i);
        const int   tok  = __ldg(subnode_ids + b * S_CONST + sub);

        const int row = b * N_CONST + node;
        const int pos = atomicAdd(&g_cursor[row], 1);
        if (pos < CAP) {
            const __half  h  = __float2half_rn(val);
            const __half2 h2 = __halves2half2(h, h);
            uint2 e;
            e.x = (unsigned)tok;
            e.y = *reinterpret_cast<const unsigned*>(&h2);
            g_bucket[(size_t)row * CAP + pos] = e;
        }
    } else {
        const size_t j = (size_t)(blk - FILL_BLOCKS) * 256 + threadIdx.x;
        if (j < CONV_ELEMS8) {
            const float4 f0 = __ldg(reinterpret_cast<const float4*>(emb_table) + 2 * j);
            const float4 f1 = __ldg(reinterpret_cast<const float4*>(emb_table) + 2 * j + 1);
            __half2 h0 = __float22half2_rn(make_float2(f0.x, f0.y));
            __half2 h1 = __float22half2_rn(make_float2(f0.z, f0.w));
            __half2 h2 = __float22half2_rn(make_float2(f1.x, f1.y));
            __half2 h3 = __float22half2_rn(make_float2(f1.z, f1.w));
            uint4 u;
            u.x = *reinterpret_cast<unsigned*>(&h0);
            u.y = *reinterpret_cast<unsigned*>(&h1);
            u.z = *reinterpret_cast<unsigned*>(&h2);
            u.w = *reinterpret_cast<unsigned*>(&h3);
            reinterpret_cast<uint4*>(g_htable)[j] = u;
        }
    }
}

// ---------------------------------------------------------------------------
// Phase 2: ONE warp per row (avg 32 entries -> fixed overhead amortized 2x
// vs the 2-warp split; no smem merge, no __syncthreads, warps fully
// decoupled). One entry = one LDG.64 by the full warp (32 lanes x 8B = the
// 256B fp16 row). 4-entry groups double-buffered -> 8 loads in flight.
// Block = 128 threads (4 warps = 4 rows), 12 blocks/SM -> 48 warps/SM.
// ---------------------------------------------------------------------------
__global__ __launch_bounds__(128, 12) void accumulate_kernel(
    float* __restrict__ out)   // [B*N, D]
{
    const int wib  = threadIdx.x >> 5;      // warp in block: 0..3
    const int row  = blockIdx.x * 4 + wib;
    const int lane = threadIdx.x & 31;      // D-halves [4*lane, 4*lane+4)

    int cnt = g_cursor[row];
    cnt = cnt < CAP ? cnt : CAP;

    const uint2* __restrict__ p = g_bucket + (size_t)row * CAP;
    const __half* __restrict__ tab = g_htable;

    float facc[4];
    #pragma unroll
    for (int q = 0; q < 4; q++) facc[q] = 0.f;

    // Group G = 4 entries; one LDG.64 per entry (full warp reads the row).
    #define LOADG(BUF, G) do {                                                  \
        _Pragma("unroll")                                                       \
        for (int L = 0; L < 4; L++) {                                           \
            const unsigned tk = __shfl_sync(0xffffffffu, e.x, (G) * 4 + L);     \
            ub[BUF][L] = *reinterpret_cast<const uint2*>(                       \
                tab + (size_t)tk * D_CONST + lane * 4);                         \
        }                                                                       \
    } while (0)

    #define CONSUME(BUF, G) do {                                                \
        __half2 h0 = __float2half2_rn(0.f), h1 = h0;                            \
        _Pragma("unroll")                                                       \
        for (int L = 0; L < 4; L++) {                                           \
            const unsigned vv = __shfl_sync(0xffffffffu, e.y, (G) * 4 + L);     \
            const __half2 v2 = *reinterpret_cast<const __half2*>(&vv);          \
            const uint2   u  = ub[BUF][L];                                      \
            h0 = __hfma2(v2, *reinterpret_cast<const __half2*>(&u.x), h0);      \
            h1 = __hfma2(v2, *reinterpret_cast<const __half2*>(&u.y), h1);      \
        }                                                                       \
        float2 f;                                                               \
        f = __half22float2(h0); facc[0] += f.x; facc[1] += f.y;                 \
        f = __half22float2(h1); facc[2] += f.x; facc[3] += f.y;                 \
    } while (0)

    for (int base = 0; base < cnt; base += 32) {
        const int rem = cnt - base;
        const int nb  = rem < 32 ? rem : 32;
        uint2 e = make_uint2(0u, 0u);                 // padding: tok 0, v 0
        if (lane < nb) e = __ldg(p + base + lane);
        const int ngrp = (nb + 3) >> 2;               // 1..8 groups of 4

        uint2 ub[2][4];

        LOADG(0, 0);
        int g = 0;
        while (true) {
            if (g + 1 < ngrp) LOADG(1, g + 1);
            CONSUME(0, g);
            g++;
            if (g >= ngrp) break;
            if (g + 1 < ngrp) LOADG(0, g + 1);
            CONSUME(1, g);
            g++;
            if (g >= ngrp) break;
        }
    }
    #undef LOADG
    #undef CONSUME

    *reinterpret_cast<float4*>(out + (size_t)row * D_CONST + lane * 4) =
        make_float4(facc[0], facc[1], facc[2], facc[3]);
    if (lane == 0) g_cursor[row] = 0;       // reset for next graph replay
}

// ---------------------------------------------------------------------------
// Inputs (metadata order):
//   0: subnode_ids [B*S] i32, 1: mask_batch [NNZ] i32, 2: mask_node [NNZ] i32,
//   3: mask_subnode [NNZ] i32, 4: mask_values [NNZ] f32, 5: emb_table [VOCAB*D] f32
// Output: [B*N*D] f32
// ---------------------------------------------------------------------------
extern "C" void kernel_launch(void* const* d_in, const int* in_sizes, int n_in,
                              void* d_out, int out_size) {
    const int*   subnode_ids  = (const int*)  d_in[0];
    const int*   mask_batch   = (const int*)  d_in[1];
    const int*   mask_node    = (const int*)  d_in[2];
    const int*   mask_subnode = (const int*)  d_in[3];
    const float* mask_values  = (const float*)d_in[4];
    const float* emb_table    = (const float*)d_in[5];
    float*       out          = (float*)d_out;

    prep_kernel<<<FILL_BLOCKS + CONV_BLOCKS, 256>>>(
        subnode_ids, mask_batch, mask_node, mask_subnode, mask_values, emb_table);

    accumulate_kernel<<<ROWS / 4, 128>>>(out);
}